// round 7
// baseline (speedup 1.0000x reference)
#include <cuda_runtime.h>
#include <math.h>

#define NC        19
#define NIMG      4
#define HWN       589824          // 768*768
#define TOTAL_PIX 2359296
#define BX        288             // blocks per image
#define BLK       256
#define GRID      (BX*NIMG)       // 1152 total blocks (<= 148*8 = 1184 resident)
#define STRIDE    (BX*BLK)        // 73728 pixels per k-step within an image
#define PPT       8               // HWN / STRIDE

// ---------------- device scratch (static, no allocations) ----------------
// All accumulators are re-zeroed at the end of each run by the blocks that
// consume them, so every launch (incl. graph replays) starts from zero.
// g_bar is monotonic and never reset.
__device__ unsigned long long g_bar;
__device__ unsigned int g_hist[NIMG][2][NC];   // [img][seg|att][class]
__device__ double g_bce[2];                    // pos,neg BCE sums
__device__ unsigned int g_cnt[2];              // pos,neg counts
__device__ float  g_coefA[NIMG][NC];           // w_seg / den_seg       (overwritten)
__device__ float  g_coefB[NIMG][NC];           // 0.1*w_att/den_att     (overwritten)
__device__ double g_edge;                      // 0.3*weighted BCE      (overwritten)
__device__ double g_accum;                     // sum coef*logp

__device__ __forceinline__ float warp_sum_f(float x) {
#pragma unroll
    for (int o = 16; o > 0; o >>= 1) x += __shfl_down_sync(0xffffffffu, x, o);
    return x;
}
__device__ __forceinline__ unsigned warp_sum_u(unsigned x) {
#pragma unroll
    for (int o = 16; o > 0; o >>= 1) x += __shfl_down_sync(0xffffffffu, x, o);
    return x;
}

// release-arrive / acquire-spin grid barrier; replay-safe (monotonic counter).
__device__ __forceinline__ void bar_arrive_wait() {
    __syncthreads();
    if (threadIdx.x == 0) {
        unsigned long long r;
        asm volatile("atom.release.gpu.global.add.u64 %0, [%1], 1;"
                     : "=l"(r) : "l"(&g_bar) : "memory");
        unsigned long long target = (r / GRID + 1ull) * (unsigned long long)GRID;
        unsigned long long v;
        do {
            asm volatile("ld.acquire.gpu.global.u64 %0, [%1];"
                         : "=l"(v) : "l"(&g_bar) : "memory");
        } while (v < target);
    }
    __syncthreads();
}

__global__ void __launch_bounds__(BLK, 8) fused_kernel(
        const float* __restrict__ segin,
        const float* __restrict__ edgein,
        const int*   __restrict__ segmask,
        const int*   __restrict__ edgemask,
        float* __restrict__ out) {
    const int tid  = threadIdx.x;
    const int lane = tid & 31;
    const int warp = tid >> 5;
    const int n    = blockIdx.y;                     // this block's image
    const int p    = blockIdx.x * BLK + tid;         // base pixel within image

    __shared__ unsigned sh_hist[2 * NC];             // this image only
    __shared__ float    sh_bp[8], sh_bn[8];
    __shared__ unsigned sh_cp[8], sh_cn[8];
    __shared__ float    shA[NC], shB[NC];
    __shared__ float    sh_red[8];

    // ---------------- phase 1: histograms + BCE + per-pixel pack ----------------
    if (tid < 2 * NC) sh_hist[tid] = 0u;
    __syncthreads();

    unsigned long long pk = 0ull;                    // 8 packed bytes in regs
    float bp = 0.f, bn = 0.f;
    unsigned cp = 0u, cn = 0u;
    unsigned cseg = 0u, catt = 0u;                   // lane c (<NC) owns class c

    {
        const size_t base = (size_t)n * HWN + p;
#pragma unroll
        for (int k = 0; k < PPT; k++) {
            const size_t idx = base + (size_t)k * STRIDE;
            int   t  = segmask[idx];
            float e  = edgein [idx];
            int   em = edgemask[idx];

            bool inb = ((unsigned)t < (unsigned)NC);
            bool vs  = (t != 255);
            bool att = (e > 0.8f);
            bool va  = vs && att;
            int  tc  = min(max(t, 0), NC - 1);

            unsigned batt = __ballot_sync(0xffffffffu, inb && att);
#pragma unroll
            for (int c = 0; c < NC; c++) {
                unsigned bs = __ballot_sync(0xffffffffu, inb && (t == c));
                if (lane == c) {
                    cseg += __popc(bs);
                    catt += __popc(bs & batt);
                }
            }
            unsigned byte = (unsigned)tc | (vs ? 32u : 0u) | (va ? 64u : 0u);
            pk |= (unsigned long long)byte << (8 * k);

            float bce = fmaxf(e, 0.f) - e * (float)em + log1pf(__expf(-fabsf(e)));
            if (em == 1)      { bp += bce; cp++; }
            else if (em == 0) { bn += bce; cn++; }
        }
    }

    if (lane < NC) {
        if (cseg) atomicAdd(&sh_hist[lane], cseg);
        if (catt) atomicAdd(&sh_hist[NC + lane], catt);
    }
    bp = warp_sum_f(bp); bn = warp_sum_f(bn);
    cp = warp_sum_u(cp); cn = warp_sum_u(cn);
    if (lane == 0) { sh_bp[warp] = bp; sh_bn[warp] = bn; sh_cp[warp] = cp; sh_cn[warp] = cn; }
    __syncthreads();

    if (tid < 2 * NC) {
        unsigned v = sh_hist[tid];
        if (v) atomicAdd(&g_hist[n][tid / NC][tid % NC], v);
    }
    if (tid == 0) {
        float tbp = 0.f, tbn = 0.f; unsigned tcp = 0, tcn = 0;
#pragma unroll
        for (int w = 0; w < 8; w++) { tbp += sh_bp[w]; tbn += sh_bn[w]; tcp += sh_cp[w]; tcn += sh_cn[w]; }
        atomicAdd(&g_bce[0], (double)tbp);
        atomicAdd(&g_bce[1], (double)tbn);
        atomicAdd(&g_cnt[0], tcp);
        atomicAdd(&g_cnt[1], tcn);
    }

    bar_arrive_wait();   // ---- barrier 1: stats complete ----

    // ---------------- phase 2: small reducer blocks ----------------
    if (blockIdx.y == 0 && blockIdx.x < NIMG) {
        const int m = blockIdx.x;
        __shared__ double sw[2 * NC];
        __shared__ double sden[2];
        if (tid < 2 * NC) {
            int which = tid / NC, c = tid % NC;
            double tot = 0.0;
            for (int cc = 0; cc < NC; cc++) tot += (double)g_hist[m][which][cc];
            double b = (double)g_hist[m][which][c];
            sw[which * NC + c] = (b != 0.0 ? (1.0 - b / tot) : 0.0) + 1.0;
        }
        __syncthreads();
        if (tid < 2) {
            double d = 0.0;
            for (int c = 0; c < NC; c++) d += (double)g_hist[m][tid][c] * sw[tid * NC + c];
            sden[tid] = d;
        }
        __syncthreads();
        if (tid < NC) {
            g_coefA[m][tid] = (float)(sw[tid] / sden[0]);
            g_coefB[m][tid] = (float)(0.1 * sw[NC + tid] / sden[1]);
        }
        __syncthreads();
        if (tid < 2 * NC) g_hist[m][tid / NC][tid % NC] = 0u;   // re-zero for replay
    } else if (blockIdx.y == 0 && blockIdx.x == NIMG && tid == 0) {
        double pos = (double)g_cnt[0], neg = (double)g_cnt[1];
        double s = pos + neg;
        g_edge = 0.3 * ((neg / s) * g_bce[0] + (pos / s) * g_bce[1]) / (double)TOTAL_PIX;
        g_bce[0] = 0.0; g_bce[1] = 0.0; g_cnt[0] = 0u; g_cnt[1] = 0u;
    }

    bar_arrive_wait();   // ---- barrier 2: coefficients published ----

    // ---------------- phase 3: single pass over segin ----------------
    if (tid < NC) {
        shA[tid] = g_coefA[n][tid];
        shB[tid] = g_coefB[n][tid];
    }
    __syncthreads();

    float acc = 0.f;
    {
        const float* sp = segin + (size_t)n * (NC * (size_t)HWN) + p;
#pragma unroll 1
        for (int k = 0; k < PPT; k++) {
            const unsigned byte = (unsigned)(pk >> (8 * k)) & 0xffu;
            const int t = (int)(byte & 31u);
            float coeff = ((byte & 32u) ? shA[t] : 0.f)
                        + ((byte & 64u) ? shB[t] : 0.f);

            float v[NC];
#pragma unroll
            for (int c = 0; c < NC; c++) v[c] = __ldg(sp + (size_t)c * HWN);

            float m = v[0];
#pragma unroll
            for (int c = 1; c < NC; c++) m = fmaxf(m, v[c]);

            float s = 0.f, vt = v[0];
#pragma unroll
            for (int c = 0; c < NC; c++) {
                s += __expf(v[c] - m);
                if (c == t) vt = v[c];
            }
            acc += coeff * (vt - m - __logf(s));
            sp += STRIDE;
        }
    }

    acc = warp_sum_f(acc);
    if (lane == 0) sh_red[warp] = acc;
    __syncthreads();
    if (tid == 0) {
        float bsum = 0.f;
#pragma unroll
        for (int w = 0; w < 8; w++) bsum += sh_red[w];
        atomicAdd(&g_accum, (double)bsum);
    }

    // ---- barrier 3: arrive; block (0,0) waits and finalizes ----
    if (blockIdx.x == 0 && blockIdx.y == 0) {
        __syncthreads();
        if (tid == 0) {
            unsigned long long r;
            asm volatile("atom.release.gpu.global.add.u64 %0, [%1], 1;"
                         : "=l"(r) : "l"(&g_bar) : "memory");
            unsigned long long target = (r / GRID + 1ull) * (unsigned long long)GRID;
            unsigned long long v;
            do {
                asm volatile("ld.acquire.gpu.global.u64 %0, [%1];"
                             : "=l"(v) : "l"(&g_bar) : "memory");
            } while (v < target);
            double a = atomicAdd(&g_accum, 0.0);
            out[0] = (float)(-a + g_edge);
            g_accum = 0.0;                          // re-zero for next replay
        }
    } else {
        __syncthreads();
        if (threadIdx.x == 0) {
            unsigned long long r;
            asm volatile("atom.release.gpu.global.add.u64 %0, [%1], 1;"
                         : "=l"(r) : "l"(&g_bar) : "memory");
            (void)r;
        }
    }
}

// ---------------- launch ----------------
extern "C" void kernel_launch(void* const* d_in, const int* in_sizes, int n_in,
                              void* d_out, int out_size) {
    const float* segin    = (const float*)d_in[0];   // [4,19,768,768] f32
    const float* edgein   = (const float*)d_in[1];   // [4,1,768,768]  f32
    const int*   segmask  = (const int*)  d_in[2];   // [4,768,768]    i32
    const int*   edgemask = (const int*)  d_in[3];   // [4,1,768,768]  i32
    float* out = (float*)d_out;

    fused_kernel<<<dim3(BX, NIMG), BLK>>>(segin, edgein, segmask, edgemask, out);
}

// round 8
// speedup vs baseline: 1.2131x; 1.2131x over previous
#include <cuda_runtime.h>
#include <math.h>

#define NC        19
#define NIMG      4
#define HWN       589824          // 768*768
#define TOTAL_PIX 2359296
#define BX        288             // blocks per image
#define BLK       256
#define GRID      (BX*NIMG)       // 1152 total blocks (<= 148*8 = 1184 resident)
#define STRIDE    (BX*BLK)        // 73728 pixels per k-step within an image
#define PPT       8               // HWN / STRIDE

// ---------------- device scratch (static, no allocations) ----------------
// All accumulators are re-zeroed at the end of each run by the blocks that
// consume them, so every launch (incl. graph replays) starts from zero.
// g_bar is monotonic and never reset.
__device__ unsigned long long g_bar;
__device__ unsigned int g_hist[NIMG][2][NC];   // [img][seg|att][class]
__device__ double g_bce[2];                    // pos,neg BCE sums
__device__ unsigned int g_cnt[2];              // pos,neg counts
__device__ float  g_coefA[NIMG][NC];           // w_seg / den_seg       (overwritten)
__device__ float  g_coefB[NIMG][NC];           // 0.1*w_att/den_att     (overwritten)
__device__ double g_edge;                      // 0.3*weighted BCE      (overwritten)
__device__ double g_accum;                     // sum coef*logp

__device__ __forceinline__ float warp_sum_f(float x) {
#pragma unroll
    for (int o = 16; o > 0; o >>= 1) x += __shfl_down_sync(0xffffffffu, x, o);
    return x;
}
__device__ __forceinline__ unsigned warp_sum_u(unsigned x) {
#pragma unroll
    for (int o = 16; o > 0; o >>= 1) x += __shfl_down_sync(0xffffffffu, x, o);
    return x;
}

// release-arrive / acquire-spin grid barrier with backoff; replay-safe.
__device__ __forceinline__ void bar_arrive_wait() {
    __syncthreads();
    if (threadIdx.x == 0) {
        unsigned long long r;
        asm volatile("atom.release.gpu.global.add.u64 %0, [%1], 1;"
                     : "=l"(r) : "l"(&g_bar) : "memory");
        unsigned long long target = (r / GRID + 1ull) * (unsigned long long)GRID;
        unsigned long long v;
        for (;;) {
            asm volatile("ld.acquire.gpu.global.u64 %0, [%1];"
                         : "=l"(v) : "l"(&g_bar) : "memory");
            if (v >= target) break;
            __nanosleep(256);               // keep 1152 pollers off the L2 slice
        }
    }
    __syncthreads();
}

__global__ void __launch_bounds__(BLK, 8) fused_kernel(
        const float* __restrict__ segin,
        const float* __restrict__ edgein,
        const int*   __restrict__ segmask,
        const int*   __restrict__ edgemask,
        float* __restrict__ out) {
    const int tid  = threadIdx.x;
    const int lane = tid & 31;
    const int warp = tid >> 5;
    const int n    = blockIdx.y;                     // this block's image
    const int p    = blockIdx.x * BLK + tid;         // base pixel within image

    __shared__ unsigned sh_hist[2 * NC];             // this image only
    __shared__ float    sh_bp[8], sh_bn[8];
    __shared__ unsigned sh_cp[8], sh_cn[8];
    __shared__ float    shA[NC], shB[NC];
    __shared__ float    sh_red[8];

    // ---------------- phase 1: histograms + BCE + per-pixel pack ----------------
    if (tid < 2 * NC) sh_hist[tid] = 0u;
    __syncthreads();

    unsigned long long pk = 0ull;                    // 8 packed bytes in regs
    float bp = 0.f, bn = 0.f;
    unsigned cp = 0u, cn = 0u;

    {
        const size_t base = (size_t)n * HWN + p;
#pragma unroll
        for (int k = 0; k < PPT; k++) {
            const size_t idx = base + (size_t)k * STRIDE;
            int   t  = segmask[idx];
            float e  = edgein [idx];
            int   em = edgemask[idx];

            bool inb = ((unsigned)t < (unsigned)NC);
            bool vs  = (t != 255);
            bool att = (e > 0.8f);
            bool va  = vs && att;
            int  tc  = min(max(t, 0), NC - 1);

            // group lanes by class: one shared atomic per distinct class per warp
            unsigned mask = __match_any_sync(0xffffffffu, t);
            unsigned batt = __ballot_sync(0xffffffffu, att);
            bool leader = (lane == (__ffs(mask) - 1));
            if (leader && inb) {
                atomicAdd(&sh_hist[t], __popc(mask));
                unsigned ca = __popc(mask & batt);
                if (ca) atomicAdd(&sh_hist[NC + t], ca);
            }

            unsigned byte = (unsigned)tc | (vs ? 32u : 0u) | (va ? 64u : 0u);
            pk |= (unsigned long long)byte << (8 * k);

            float bce = fmaxf(e, 0.f) - e * (float)em + log1pf(__expf(-fabsf(e)));
            if (em == 1)      { bp += bce; cp++; }
            else if (em == 0) { bn += bce; cn++; }
        }
    }

    bp = warp_sum_f(bp); bn = warp_sum_f(bn);
    cp = warp_sum_u(cp); cn = warp_sum_u(cn);
    if (lane == 0) { sh_bp[warp] = bp; sh_bn[warp] = bn; sh_cp[warp] = cp; sh_cn[warp] = cn; }
    __syncthreads();

    if (tid < 2 * NC) {
        unsigned v = sh_hist[tid];
        if (v) atomicAdd(&g_hist[n][tid / NC][tid % NC], v);
    }
    if (tid == 0) {
        float tbp = 0.f, tbn = 0.f; unsigned tcp = 0, tcn = 0;
#pragma unroll
        for (int w = 0; w < 8; w++) { tbp += sh_bp[w]; tbn += sh_bn[w]; tcp += sh_cp[w]; tcn += sh_cn[w]; }
        atomicAdd(&g_bce[0], (double)tbp);
        atomicAdd(&g_bce[1], (double)tbn);
        atomicAdd(&g_cnt[0], tcp);
        atomicAdd(&g_cnt[1], tcn);
    }

    bar_arrive_wait();   // ---- barrier 1: stats complete ----

    // ---------------- phase 2: small reducer blocks ----------------
    if (blockIdx.y == 0 && blockIdx.x < NIMG) {
        const int m = blockIdx.x;
        __shared__ double sw[2 * NC];
        __shared__ double sden[2];
        if (tid < 2 * NC) {
            int which = tid / NC, c = tid % NC;
            double tot = 0.0;
            for (int cc = 0; cc < NC; cc++) tot += (double)g_hist[m][which][cc];
            double b = (double)g_hist[m][which][c];
            sw[which * NC + c] = (b != 0.0 ? (1.0 - b / tot) : 0.0) + 1.0;
        }
        __syncthreads();
        if (tid < 2) {
            double d = 0.0;
            for (int c = 0; c < NC; c++) d += (double)g_hist[m][tid][c] * sw[tid * NC + c];
            sden[tid] = d;
        }
        __syncthreads();
        if (tid < NC) {
            g_coefA[m][tid] = (float)(sw[tid] / sden[0]);
            g_coefB[m][tid] = (float)(0.1 * sw[NC + tid] / sden[1]);
        }
        __syncthreads();
        if (tid < 2 * NC) g_hist[m][tid / NC][tid % NC] = 0u;   // re-zero for replay
    } else if (blockIdx.y == 0 && blockIdx.x == NIMG && tid == 0) {
        double pos = (double)g_cnt[0], neg = (double)g_cnt[1];
        double s = pos + neg;
        g_edge = 0.3 * ((neg / s) * g_bce[0] + (pos / s) * g_bce[1]) / (double)TOTAL_PIX;
        g_bce[0] = 0.0; g_bce[1] = 0.0; g_cnt[0] = 0u; g_cnt[1] = 0u;
    }

    bar_arrive_wait();   // ---- barrier 2: coefficients published ----

    // ---------------- phase 3: single pass over segin ----------------
    if (tid < NC) {
        shA[tid] = g_coefA[n][tid];
        shB[tid] = g_coefB[n][tid];
    }
    __syncthreads();

    float acc = 0.f;
    {
        const float* sp = segin + (size_t)n * (NC * (size_t)HWN) + p;
#pragma unroll 1
        for (int k = 0; k < PPT; k++) {
            const unsigned byte = (unsigned)(pk >> (8 * k)) & 0xffu;
            const int t = (int)(byte & 31u);
            float coeff = ((byte & 32u) ? shA[t] : 0.f)
                        + ((byte & 64u) ? shB[t] : 0.f);

            float v[NC];
#pragma unroll
            for (int c = 0; c < NC; c++) v[c] = __ldg(sp + (size_t)c * HWN);

            float m = v[0];
#pragma unroll
            for (int c = 1; c < NC; c++) m = fmaxf(m, v[c]);

            float s = 0.f, vt = v[0];
#pragma unroll
            for (int c = 0; c < NC; c++) {
                s += __expf(v[c] - m);
                if (c == t) vt = v[c];
            }
            acc += coeff * (vt - m - __logf(s));
            sp += STRIDE;
        }
    }

    acc = warp_sum_f(acc);
    if (lane == 0) sh_red[warp] = acc;
    __syncthreads();
    if (tid == 0) {
        float bsum = 0.f;
#pragma unroll
        for (int w = 0; w < 8; w++) bsum += sh_red[w];
        atomicAdd(&g_accum, (double)bsum);
    }

    // ---- barrier 3: arrive; block (0,0) waits and finalizes ----
    if (blockIdx.x == 0 && blockIdx.y == 0) {
        __syncthreads();
        if (tid == 0) {
            unsigned long long r;
            asm volatile("atom.release.gpu.global.add.u64 %0, [%1], 1;"
                         : "=l"(r) : "l"(&g_bar) : "memory");
            unsigned long long target = (r / GRID + 1ull) * (unsigned long long)GRID;
            unsigned long long v;
            for (;;) {
                asm volatile("ld.acquire.gpu.global.u64 %0, [%1];"
                             : "=l"(v) : "l"(&g_bar) : "memory");
                if (v >= target) break;
                __nanosleep(256);
            }
            double a = atomicAdd(&g_accum, 0.0);
            out[0] = (float)(-a + g_edge);
            g_accum = 0.0;                          // re-zero for next replay
        }
    } else {
        __syncthreads();
        if (threadIdx.x == 0) {
            unsigned long long r;
            asm volatile("atom.release.gpu.global.add.u64 %0, [%1], 1;"
                         : "=l"(r) : "l"(&g_bar) : "memory");
            (void)r;
        }
    }
}

// ---------------- launch ----------------
extern "C" void kernel_launch(void* const* d_in, const int* in_sizes, int n_in,
                              void* d_out, int out_size) {
    const float* segin    = (const float*)d_in[0];   // [4,19,768,768] f32
    const float* edgein   = (const float*)d_in[1];   // [4,1,768,768]  f32
    const int*   segmask  = (const int*)  d_in[2];   // [4,768,768]    i32
    const int*   edgemask = (const int*)  d_in[3];   // [4,1,768,768]  i32
    float* out = (float*)d_out;

    fused_kernel<<<dim3(BX, NIMG), BLK>>>(segin, edgein, segmask, edgemask, out);
}

// round 14
// speedup vs baseline: 1.2138x; 1.0005x over previous
#include <cuda_runtime.h>
#include <math.h>

#define NC        19
#define NIMG      4
#define HWN       589824          // 768*768
#define TOTAL_PIX 2359296

// ---------------- device scratch (static, no allocations) ----------------
// Replay-safe zeroing: weights_kernel zeroes g_hist/g_bce/g_cnt after use;
// final_kernel zeroes g_accum after use. Static init covers the first run.
__device__ unsigned int  g_hist[NIMG][2][NC];   // [img][seg|att][class]
__device__ double        g_bce[2];              // pos,neg BCE sums
__device__ unsigned int  g_cnt[2];              // pos,neg counts
__device__ float         g_coefA[NIMG][NC];     // w_seg / den_seg     (overwritten)
__device__ float         g_coefB[NIMG][NC];     // 0.1*w_att/den_att   (overwritten)
__device__ double        g_edge;                // 0.3*weighted BCE    (overwritten)
__device__ double        g_accum;               // sum coef*logp
__device__ unsigned char g_pack[TOTAL_PIX];     // class|seg_valid<<5|att_valid<<6

__device__ __forceinline__ float warp_sum_f(float x) {
#pragma unroll
    for (int o = 16; o > 0; o >>= 1) x += __shfl_down_sync(0xffffffffu, x, o);
    return x;
}
__device__ __forceinline__ unsigned warp_sum_u(unsigned x) {
#pragma unroll
    for (int o = 16; o > 0; o >>= 1) x += __shfl_down_sync(0xffffffffu, x, o);
    return x;
}

// ---------------- kernel 1: histograms + BCE + per-pixel pack ----------------
// grid = (256, NIMG), block = 256. Each thread handles exactly 9 pixels.
__global__ void __launch_bounds__(256) stats_kernel(
        const float* __restrict__ edgein,
        const int*   __restrict__ segmask,
        const int*   __restrict__ edgemask) {
    const int n    = blockIdx.y;
    const int tid  = threadIdx.x;
    const int lane = tid & 31;
    const int warp = tid >> 5;
    const size_t base = (size_t)n * HWN;
    const int gid = blockIdx.x * 256 + tid;      // [0, 65536)

    __shared__ unsigned sh_hist[2 * NC];
    __shared__ float sh_bp[8], sh_bn[8];
    __shared__ unsigned sh_cp[8], sh_cn[8];

    if (tid < 2 * NC) sh_hist[tid] = 0u;
    __syncthreads();

    float bp = 0.f, bn = 0.f;
    unsigned cp = 0u, cn = 0u;

#pragma unroll 1
    for (int k = 0; k < 9; k++) {
        const size_t idx = base + (size_t)(k * 65536 + gid);   // < HWN exactly
        int   t  = segmask[idx];
        float e  = edgein [idx];
        int   em = edgemask[idx];

        bool inb = ((unsigned)t < (unsigned)NC);
        bool vs  = (t != 255);
        bool att = (e > 0.8f);
        bool va  = vs && att;
        int  tc  = min(max(t, 0), NC - 1);

        // one shared atomic per distinct class per warp
        unsigned mask = __match_any_sync(0xffffffffu, t);
        unsigned batt = __ballot_sync(0xffffffffu, att);
        bool leader = (lane == (__ffs(mask) - 1));
        if (leader && inb) {
            atomicAdd(&sh_hist[t], __popc(mask));
            unsigned ca = __popc(mask & batt);
            if (ca) atomicAdd(&sh_hist[NC + t], ca);
        }

        g_pack[idx] = (unsigned char)((unsigned)tc | (vs ? 32u : 0u) | (va ? 64u : 0u));

        float bce = fmaxf(e, 0.f) - e * (float)em + log1pf(__expf(-fabsf(e)));
        if (em == 1)      { bp += bce; cp++; }
        else if (em == 0) { bn += bce; cn++; }
    }

    bp = warp_sum_f(bp); bn = warp_sum_f(bn);
    cp = warp_sum_u(cp); cn = warp_sum_u(cn);
    if (lane == 0) { sh_bp[warp] = bp; sh_bn[warp] = bn; sh_cp[warp] = cp; sh_cn[warp] = cn; }
    __syncthreads();

    if (tid < 2 * NC) {
        unsigned v = sh_hist[tid];
        if (v) atomicAdd(&g_hist[n][tid / NC][tid % NC], v);
    }
    if (tid == 0) {
        float tbp = 0.f, tbn = 0.f; unsigned tcp = 0, tcn = 0;
#pragma unroll
        for (int w = 0; w < 8; w++) { tbp += sh_bp[w]; tbn += sh_bn[w]; tcp += sh_cp[w]; tcn += sh_cn[w]; }
        atomicAdd(&g_bce[0], (double)tbp);
        atomicAdd(&g_bce[1], (double)tbn);
        atomicAdd(&g_cnt[0], tcp);
        atomicAdd(&g_cnt[1], tcn);
    }
}

// ---------------- kernel 2: coefficients + edge term, then self-zero ----------------
__global__ void weights_kernel() {
    const int tid = threadIdx.x;                  // 1 block, 256 threads
    __shared__ double wseg[NIMG][NC], watt[NIMG][NC];
    __shared__ double den_seg[NIMG], den_att[NIMG];

    if (tid < NIMG * NC) {
        int n = tid / NC, c = tid % NC;
        double tot_s = 0.0, tot_a = 0.0;
        for (int cc = 0; cc < NC; cc++) {
            tot_s += (double)g_hist[n][0][cc];
            tot_a += (double)g_hist[n][1][cc];
        }
        double bs = (double)g_hist[n][0][c];
        double ba = (double)g_hist[n][1][c];
        wseg[n][c] = (bs != 0.0 ? (1.0 - bs / tot_s) : 0.0) + 1.0;
        watt[n][c] = (ba != 0.0 ? (1.0 - ba / tot_a) : 0.0) + 1.0;
    }
    __syncthreads();
    if (tid < NIMG) {
        double ds = 0.0, da = 0.0;
        for (int c = 0; c < NC; c++) {
            ds += (double)g_hist[tid][0][c] * wseg[tid][c];
            da += (double)g_hist[tid][1][c] * watt[tid][c];
        }
        den_seg[tid] = ds; den_att[tid] = da;
    }
    __syncthreads();
    if (tid < NIMG * NC) {
        int n = tid / NC, c = tid % NC;
        g_coefA[n][c] = (float)(wseg[n][c] / den_seg[n]);
        g_coefB[n][c] = (float)(0.1 * watt[n][c] / den_att[n]);
    }
    if (tid == 0) {
        double pos = (double)g_cnt[0], neg = (double)g_cnt[1];
        double s = pos + neg;
        g_edge = 0.3 * ((neg / s) * g_bce[0] + (pos / s) * g_bce[1]) / (double)TOTAL_PIX;
        g_bce[0] = 0.0; g_bce[1] = 0.0; g_cnt[0] = 0u; g_cnt[1] = 0u;
    }
    // re-zero histograms for the next replay
    if (tid < NIMG * 2 * NC) ((unsigned*)g_hist)[tid] = 0u;
}

// ---------------- kernel 3: main pass over segin ----------------
// grid = (2304, NIMG), block = 256 : one pixel per thread (R3 structure, 6.1 TB/s).
__global__ void __launch_bounds__(256) main_kernel(
        const float* __restrict__ segin) {
    const int n   = blockIdx.y;
    const int pix = blockIdx.x * 256 + threadIdx.x;   // < HWN exactly
    const size_t pb = (size_t)n * HWN + pix;

    __shared__ float shA[NC], shB[NC];
    if (threadIdx.x < NC) {
        shA[threadIdx.x] = g_coefA[n][threadIdx.x];
        shB[threadIdx.x] = g_coefB[n][threadIdx.x];
    }
    __syncthreads();

    const unsigned byte = (unsigned)g_pack[pb];
    const int t = (int)(byte & 31u);
    const float coeff = ((byte & 32u) ? shA[t] : 0.f)
                      + ((byte & 64u) ? shB[t] : 0.f);

    const float* sp = segin + (size_t)n * (NC * (size_t)HWN) + pix;

    float v[NC];
#pragma unroll
    for (int c = 0; c < NC; c++) v[c] = __ldg(sp + (size_t)c * HWN);

    float m = v[0];
#pragma unroll
    for (int c = 1; c < NC; c++) m = fmaxf(m, v[c]);

    float s = 0.f, vt = v[0];
#pragma unroll
    for (int c = 0; c < NC; c++) {
        s += __expf(v[c] - m);
        if (c == t) vt = v[c];
    }
    float contrib = coeff * (vt - m - __logf(s));

    __shared__ float sh_red[8];
    contrib = warp_sum_f(contrib);
    if ((threadIdx.x & 31) == 0) sh_red[threadIdx.x >> 5] = contrib;
    __syncthreads();
    if (threadIdx.x == 0) {
        float bsum = 0.f;
#pragma unroll
        for (int w = 0; w < 8; w++) bsum += sh_red[w];
        atomicAdd(&g_accum, (double)bsum);
    }
}

// ---------------- kernel 4: final scalar + self-zero ----------------
__global__ void final_kernel(float* out) {
    out[0] = (float)(-g_accum + g_edge);
    g_accum = 0.0;
}

// ---------------- launch ----------------
extern "C" void kernel_launch(void* const* d_in, const int* in_sizes, int n_in,
                              void* d_out, int out_size) {
    const float* segin    = (const float*)d_in[0];   // [4,19,768,768] f32
    const float* edgein   = (const float*)d_in[1];   // [4,1,768,768]  f32
    const int*   segmask  = (const int*)  d_in[2];   // [4,768,768]    i32
    const int*   edgemask = (const int*)  d_in[3];   // [4,1,768,768]  i32
    float* out = (float*)d_out;

    stats_kernel<<<dim3(256, NIMG), 256>>>(edgein, segmask, edgemask);
    weights_kernel<<<1, 256>>>();
    main_kernel<<<dim3(HWN / 256, NIMG), 256>>>(segin);
    final_kernel<<<1, 1>>>(out);
}